// round 3
// baseline (speedup 1.0000x reference)
#include <cuda_runtime.h>
#include <math.h>
#include <stdint.h>

// ---- problem dims ----
#define TD 2048      // hidden
#define TI 1024      // intermediate
#define NE 32        // experts
#define KE 8         // top-k
#define NT 8192      // tokens (4*2048)
#define NP (NT*KE)   // 65536 token-expert pairs

// ---- GEMM tiles ----
#define BM 64
#define BN 64
#define BK 16
#define NTHREADS 128
#define APAD 20      // smem row stride for A tiles (conflict-free frag loads)
#define BPAD 68      // smem row stride for B tiles

// ---- scratch (no allocations allowed -> __device__ globals) ----
__device__ int   d_cnt[NE];
__device__ int   d_off[NE+1];
__device__ int   d_cursor[NE];
__device__ int   d_topi[NT*KE];
__device__ float d_topw[NT*KE];
__device__ float d_probs[NT*NE];
__device__ int   d_ltok[NP];
__device__ float d_lw[NP];
__device__ int   d_ppos[NT*KE];
__device__ float d_h[(size_t)NP*TI];   // 256 MiB
__device__ float d_y[(size_t)NP*TD];   // 512 MiB

// ======================================================================
// helpers
// ======================================================================
__device__ __forceinline__ uint32_t f2tf32(float x) {
    uint32_t r;
    asm("cvt.rna.tf32.f32 %0, %1;" : "=r"(r) : "f"(x));
    return r;
}

__device__ __forceinline__ void mma_tf32(float c[4], const uint32_t a[4], const uint32_t b[2]) {
    asm volatile(
        "mma.sync.aligned.m16n8k8.row.col.f32.tf32.tf32.f32 "
        "{%0,%1,%2,%3}, {%4,%5,%6,%7}, {%8,%9}, {%0,%1,%2,%3};\n"
        : "+f"(c[0]), "+f"(c[1]), "+f"(c[2]), "+f"(c[3])
        : "r"(a[0]), "r"(a[1]), "r"(a[2]), "r"(a[3]), "r"(b[0]), "r"(b[1]));
}

// ======================================================================
// 0) init scratch counters
// ======================================================================
__global__ void k_init() {
    int i = threadIdx.x;
    if (i < NE) { d_cnt[i] = 0; d_cursor[i] = 0; }
}

// ======================================================================
// 1) router: logits, top-8 (lower-index tie-break), softmax(top-k),
//    full softmax probs (for aux), per-expert counts
// ======================================================================
__global__ void k_router(const float* __restrict__ X, const float* __restrict__ Wgate) {
    int warp = threadIdx.x >> 5, lane = threadIdx.x & 31;
    int t = blockIdx.x * 8 + warp;
    __shared__ int scnt[NE];
    if (threadIdx.x < NE) scnt[threadIdx.x] = 0;
    __syncthreads();

    const float4* x4 = (const float4*)(X + (size_t)t * TD);
    float acc = 0.f;
    #pragma unroll 4
    for (int d4 = 0; d4 < TD / 4; d4++) {
        float4 xv = __ldg(&x4[d4]);
        int d = d4 * 4;
        acc += xv.x * __ldg(&Wgate[(d + 0) * NE + lane]);
        acc += xv.y * __ldg(&Wgate[(d + 1) * NE + lane]);
        acc += xv.z * __ldg(&Wgate[(d + 2) * NE + lane]);
        acc += xv.w * __ldg(&Wgate[(d + 3) * NE + lane]);
    }
    float vo = acc;     // original logit for expert==lane
    float v  = acc;     // working copy for top-k

    float topv[KE]; int topidx[KE];
    #pragma unroll
    for (int k = 0; k < KE; k++) {
        float mv = v; int mi = lane;
        #pragma unroll
        for (int off = 16; off > 0; off >>= 1) {
            float ov = __shfl_xor_sync(0xffffffffu, mv, off);
            int   oi = __shfl_xor_sync(0xffffffffu, mi, off);
            if (ov > mv || (ov == mv && oi < mi)) { mv = ov; mi = oi; }
        }
        topv[k] = mv; topidx[k] = mi;
        if (lane == mi) v = -INFINITY;
    }

    // softmax over the selected 8
    float m = topv[0];
    float s = 0.f;
    #pragma unroll
    for (int k = 0; k < KE; k++) s += expf(topv[k] - m);
    #pragma unroll
    for (int k = 0; k < KE; k++) {
        if (lane == k) {
            d_topi[t * KE + k] = topidx[k];
            d_topw[t * KE + k] = expf(topv[k] - m) / s;
        }
        if (lane == 0) atomicAdd(&scnt[topidx[k]], 1);
    }

    // full-softmax probs for aux loss
    float pe = expf(vo - m);
    float ps = pe;
    #pragma unroll
    for (int off = 16; off > 0; off >>= 1) ps += __shfl_xor_sync(0xffffffffu, ps, off);
    d_probs[t * NE + lane] = pe / ps;

    __syncthreads();
    if (threadIdx.x < NE) atomicAdd(&d_cnt[threadIdx.x], scnt[threadIdx.x]);
}

// ======================================================================
// 2) exclusive scan of counts (tiny)
// ======================================================================
__global__ void k_scan() {
    if (threadIdx.x == 0) {
        int s = 0;
        for (int e = 0; e < NE; e++) { d_off[e] = s; s += d_cnt[e]; }
        d_off[NE] = s;
    }
}

// ======================================================================
// 3) build per-expert token lists + pair-position index (gather combine)
// ======================================================================
__global__ void k_build() {
    int i = blockIdx.x * blockDim.x + threadIdx.x;
    if (i >= NP) return;
    int e   = d_topi[i];
    int pos = atomicAdd(&d_cursor[e], 1);
    int idx = d_off[e] + pos;
    d_ltok[idx] = i >> 3;     // token id
    d_lw[idx]   = d_topw[i];
    d_ppos[i]   = idx;
}

// ======================================================================
// 4) pass A: h = silu(X_e @ Wg_e) * (X_e @ Wu_e), gathered rows, tf32 mma
//    grid: (TI/BN, NT/BM, NE)
// ======================================================================
__global__ __launch_bounds__(NTHREADS) void k_gateup(const float* __restrict__ X,
                                                     const float* __restrict__ Wg,
                                                     const float* __restrict__ Wu) {
    int e  = blockIdx.z;
    int Ce = d_cnt[e];
    int m0 = blockIdx.y * BM;
    if (m0 >= Ce) return;
    int n0   = blockIdx.x * BN;
    int gOff = d_off[e];
    const float* Bg = Wg + (size_t)e * TD * TI;
    const float* Bu = Wu + (size_t)e * TD * TI;

    __shared__ uint32_t sA [2][BM * APAD];
    __shared__ uint32_t sBg[2][BK * BPAD];
    __shared__ uint32_t sBu[2][BK * BPAD];

    int tid = threadIdx.x;
    int lane = tid & 31, warp = tid >> 5;
    int wm = warp & 1, wn = warp >> 1;
    int g = lane >> 2, tg = lane & 3;

    // A loader: 64 rows x 4 float4 = 256 float4, 2 per thread
    int arow[2], acol[2];
    const float4* aptr[2];
    #pragma unroll
    for (int j = 0; j < 2; j++) {
        int lin = tid + j * 128;
        arow[j] = lin >> 2;
        acol[j] = (lin & 3) * 4;
        int r = m0 + arow[j]; if (r >= Ce) r = Ce - 1;
        int tok = d_ltok[gOff + r];
        aptr[j] = (const float4*)(X + (size_t)tok * TD + acol[j]);
    }
    // B loader: 16 rows x 16 float4 = 256 float4, 2 per thread (per matrix)
    int brow[2], bcol[2];
    #pragma unroll
    for (int j = 0; j < 2; j++) {
        int lin = tid + j * 128;
        brow[j] = lin >> 4;
        bcol[j] = (lin & 15) * 4;
    }

    float cg[2][4][4], cu[2][4][4];
    #pragma unroll
    for (int a = 0; a < 2; a++)
        #pragma unroll
        for (int b = 0; b < 4; b++)
            #pragma unroll
            for (int c = 0; c < 4; c++) { cg[a][b][c] = 0.f; cu[a][b][c] = 0.f; }

    const int KT = TD / BK;  // 128
    float4 ra[2], rg[2], ru[2];

    // prologue: load tile 0
    #pragma unroll
    for (int j = 0; j < 2; j++) {
        ra[j] = __ldg(aptr[j]);
        rg[j] = __ldg((const float4*)(Bg + (size_t)brow[j] * TI + n0 + bcol[j]));
        ru[j] = __ldg((const float4*)(Bu + (size_t)brow[j] * TI + n0 + bcol[j]));
    }
    #pragma unroll
    for (int j = 0; j < 2; j++) {
        uint32_t* pa = &sA[0][arow[j] * APAD + acol[j]];
        pa[0] = f2tf32(ra[j].x); pa[1] = f2tf32(ra[j].y); pa[2] = f2tf32(ra[j].z); pa[3] = f2tf32(ra[j].w);
        uint32_t* pg = &sBg[0][brow[j] * BPAD + bcol[j]];
        pg[0] = f2tf32(rg[j].x); pg[1] = f2tf32(rg[j].y); pg[2] = f2tf32(rg[j].z); pg[3] = f2tf32(rg[j].w);
        uint32_t* pu = &sBu[0][brow[j] * BPAD + bcol[j]];
        pu[0] = f2tf32(ru[j].x); pu[1] = f2tf32(ru[j].y); pu[2] = f2tf32(ru[j].z); pu[3] = f2tf32(ru[j].w);
    }
    __syncthreads();

    for (int kt = 0; kt < KT; kt++) {
        int buf = kt & 1;
        if (kt + 1 < KT) {
            int k0 = (kt + 1) * BK;
            #pragma unroll
            for (int j = 0; j < 2; j++) {
                ra[j] = __ldg(aptr[j] + (k0 >> 2));
                rg[j] = __ldg((const float4*)(Bg + (size_t)(k0 + brow[j]) * TI + n0 + bcol[j]));
                ru[j] = __ldg((const float4*)(Bu + (size_t)(k0 + brow[j]) * TI + n0 + bcol[j]));
            }
        }
        // compute on buf
        #pragma unroll
        for (int ks = 0; ks < 2; ks++) {
            int kk = ks * 8;
            uint32_t afr[2][4];
            #pragma unroll
            for (int mf = 0; mf < 2; mf++) {
                int r = wm * 32 + mf * 16;
                afr[mf][0] = sA[buf][(r + g)     * APAD + kk + tg];
                afr[mf][1] = sA[buf][(r + g + 8) * APAD + kk + tg];
                afr[mf][2] = sA[buf][(r + g)     * APAD + kk + tg + 4];
                afr[mf][3] = sA[buf][(r + g + 8) * APAD + kk + tg + 4];
            }
            uint32_t bfg[4][2], bfu[4][2];
            #pragma unroll
            for (int nf = 0; nf < 4; nf++) {
                int c = wn * 32 + nf * 8 + g;
                bfg[nf][0] = sBg[buf][(kk + tg)     * BPAD + c];
                bfg[nf][1] = sBg[buf][(kk + tg + 4) * BPAD + c];
                bfu[nf][0] = sBu[buf][(kk + tg)     * BPAD + c];
                bfu[nf][1] = sBu[buf][(kk + tg + 4) * BPAD + c];
            }
            #pragma unroll
            for (int mf = 0; mf < 2; mf++)
                #pragma unroll
                for (int nf = 0; nf < 4; nf++) {
                    mma_tf32(cg[mf][nf], afr[mf], bfg[nf]);
                    mma_tf32(cu[mf][nf], afr[mf], bfu[nf]);
                }
        }
        if (kt + 1 < KT) {
            int nb = buf ^ 1;
            #pragma unroll
            for (int j = 0; j < 2; j++) {
                uint32_t* pa = &sA[nb][arow[j] * APAD + acol[j]];
                pa[0] = f2tf32(ra[j].x); pa[1] = f2tf32(ra[j].y); pa[2] = f2tf32(ra[j].z); pa[3] = f2tf32(ra[j].w);
                uint32_t* pg = &sBg[nb][brow[j] * BPAD + bcol[j]];
                pg[0] = f2tf32(rg[j].x); pg[1] = f2tf32(rg[j].y); pg[2] = f2tf32(rg[j].z); pg[3] = f2tf32(rg[j].w);
                uint32_t* pu = &sBu[nb][brow[j] * BPAD + bcol[j]];
                pu[0] = f2tf32(ru[j].x); pu[1] = f2tf32(ru[j].y); pu[2] = f2tf32(ru[j].z); pu[3] = f2tf32(ru[j].w);
            }
        }
        __syncthreads();
    }

    // epilogue: fused SiLU * up -> h
    #pragma unroll
    for (int mf = 0; mf < 2; mf++) {
        #pragma unroll
        for (int nf = 0; nf < 4; nf++) {
            int r0 = wm * 32 + mf * 16 + g;
            int c  = n0 + wn * 32 + nf * 8 + tg * 2;
            #pragma unroll
            for (int hh = 0; hh < 2; hh++) {
                int r = r0 + hh * 8;
                int grow = m0 + r;
                if (grow < Ce) {
                    float g0 = cg[mf][nf][hh * 2 + 0], g1 = cg[mf][nf][hh * 2 + 1];
                    float u0 = cu[mf][nf][hh * 2 + 0], u1 = cu[mf][nf][hh * 2 + 1];
                    float s0 = g0 / (1.f + __expf(-g0)) * u0;
                    float s1 = g1 / (1.f + __expf(-g1)) * u1;
                    *(float2*)&d_h[(size_t)(gOff + grow) * TI + c] = make_float2(s0, s1);
                }
            }
        }
    }
}

// ======================================================================
// 5) pass B: y = (w * h) @ Wd_e     grid: (TD/BN, NT/BM, NE)
// ======================================================================
__global__ __launch_bounds__(NTHREADS) void k_down(const float* __restrict__ Wd) {
    int e  = blockIdx.z;
    int Ce = d_cnt[e];
    int m0 = blockIdx.y * BM;
    if (m0 >= Ce) return;
    int n0   = blockIdx.x * BN;
    int gOff = d_off[e];
    const float* Bw = Wd + (size_t)e * TI * TD;

    __shared__ uint32_t sA[2][BM * APAD];
    __shared__ uint32_t sB[2][BK * BPAD];

    int tid = threadIdx.x;
    int lane = tid & 31, warp = tid >> 5;
    int wm = warp & 1, wn = warp >> 1;
    int g = lane >> 2, tg = lane & 3;

    int arow[2], acol[2];
    const float4* aptr[2];
    #pragma unroll
    for (int j = 0; j < 2; j++) {
        int lin = tid + j * 128;
        arow[j] = lin >> 2;
        acol[j] = (lin & 3) * 4;
        int r = m0 + arow[j]; if (r >= Ce) r = Ce - 1;
        aptr[j] = (const float4*)(d_h + (size_t)(gOff + r) * TI + acol[j]);
    }
    int brow[2], bcol[2];
    #pragma unroll
    for (int j = 0; j < 2; j++) {
        int lin = tid + j * 128;
        brow[j] = lin >> 4;
        bcol[j] = (lin & 15) * 4;
    }

    float cc[2][4][4];
    #pragma unroll
    for (int a = 0; a < 2; a++)
        #pragma unroll
        for (int b = 0; b < 4; b++)
            #pragma unroll
            for (int c = 0; c < 4; c++) cc[a][b][c] = 0.f;

    const int KT = TI / BK;  // 64
    float4 ra[2], rb[2];

    #pragma unroll
    for (int j = 0; j < 2; j++) {
        ra[j] = __ldg(aptr[j]);
        rb[j] = __ldg((const float4*)(Bw + (size_t)brow[j] * TD + n0 + bcol[j]));
    }
    #pragma unroll
    for (int j = 0; j < 2; j++) {
        uint32_t* pa = &sA[0][arow[j] * APAD + acol[j]];
        pa[0] = f2tf32(ra[j].x); pa[1] = f2tf32(ra[j].y); pa[2] = f2tf32(ra[j].z); pa[3] = f2tf32(ra[j].w);
        uint32_t* pb = &sB[0][brow[j] * BPAD + bcol[j]];
        pb[0] = f2tf32(rb[j].x); pb[1] = f2tf32(rb[j].y); pb[2] = f2tf32(rb[j].z); pb[3] = f2tf32(rb[j].w);
    }
    __syncthreads();

    for (int kt = 0; kt < KT; kt++) {
        int buf = kt & 1;
        if (kt + 1 < KT) {
            int k0 = (kt + 1) * BK;
            #pragma unroll
            for (int j = 0; j < 2; j++) {
                ra[j] = __ldg(aptr[j] + (k0 >> 2));
                rb[j] = __ldg((const float4*)(Bw + (size_t)(k0 + brow[j]) * TD + n0 + bcol[j]));
            }
        }
        #pragma unroll
        for (int ks = 0; ks < 2; ks++) {
            int kk = ks * 8;
            uint32_t afr[2][4];
            #pragma unroll
            for (int mf = 0; mf < 2; mf++) {
                int r = wm * 32 + mf * 16;
                afr[mf][0] = sA[buf][(r + g)     * APAD + kk + tg];
                afr[mf][1] = sA[buf][(r + g + 8) * APAD + kk + tg];
                afr[mf][2] = sA[buf][(r + g)     * APAD + kk + tg + 4];
                afr[mf][3] = sA[buf][(r + g + 8) * APAD + kk + tg + 4];
            }
            uint32_t bfr[4][2];
            #pragma unroll
            for (int nf = 0; nf < 4; nf++) {
                int c = wn * 32 + nf * 8 + g;
                bfr[nf][0] = sB[buf][(kk + tg)     * BPAD + c];
                bfr[nf][1] = sB[buf][(kk + tg + 4) * BPAD + c];
            }
            #pragma unroll
            for (int mf = 0; mf < 2; mf++)
                #pragma unroll
                for (int nf = 0; nf < 4; nf++)
                    mma_tf32(cc[mf][nf], afr[mf], bfr[nf]);
        }
        if (kt + 1 < KT) {
            int nb = buf ^ 1;
            #pragma unroll
            for (int j = 0; j < 2; j++) {
                uint32_t* pa = &sA[nb][arow[j] * APAD + acol[j]];
                pa[0] = f2tf32(ra[j].x); pa[1] = f2tf32(ra[j].y); pa[2] = f2tf32(ra[j].z); pa[3] = f2tf32(ra[j].w);
                uint32_t* pb = &sB[nb][brow[j] * BPAD + bcol[j]];
                pb[0] = f2tf32(rb[j].x); pb[1] = f2tf32(rb[j].y); pb[2] = f2tf32(rb[j].z); pb[3] = f2tf32(rb[j].w);
            }
        }
        __syncthreads();
    }

    // epilogue: scale by router weight, store y
    #pragma unroll
    for (int mf = 0; mf < 2; mf++) {
        #pragma unroll
        for (int nf = 0; nf < 4; nf++) {
            int r0 = wm * 32 + mf * 16 + g;
            int c  = n0 + wn * 32 + nf * 8 + tg * 2;
            #pragma unroll
            for (int hh = 0; hh < 2; hh++) {
                int grow = m0 + r0 + hh * 8;
                if (grow < Ce) {
                    float w = d_lw[gOff + grow];
                    float v0 = w * cc[mf][nf][hh * 2 + 0];
                    float v1 = w * cc[mf][nf][hh * 2 + 1];
                    *(float2*)&d_y[(size_t)(gOff + grow) * TD + c] = make_float2(v0, v1);
                }
            }
        }
    }
}

// ======================================================================
// 6) combine: out[t] = sum_k y[pairpos(t,k)]   (gather, deterministic)
// ======================================================================
__global__ void k_combine(float* __restrict__ out) {
    int t = blockIdx.x;
    __shared__ int pp[KE];
    if (threadIdx.x < KE) pp[threadIdx.x] = d_ppos[t * KE + threadIdx.x];
    __syncthreads();
    int tid = threadIdx.x;  // 256 threads
    #pragma unroll
    for (int part = 0; part < 2; part++) {
        int c4 = tid + part * 256;  // float4 index within row (512 total)
        float4 acc = make_float4(0.f, 0.f, 0.f, 0.f);
        #pragma unroll
        for (int k = 0; k < KE; k++) {
            float4 v = __ldg((const float4*)&d_y[(size_t)pp[k] * TD] + c4);
            acc.x += v.x; acc.y += v.y; acc.z += v.z; acc.w += v.w;
        }
        ((float4*)(out + (size_t)t * TD))[c4] = acc;
    }
}

// ======================================================================
// 7) aux loss = sum_e mean_t(probs[t,e]) * cnt_e / T   (deterministic)
// ======================================================================
__global__ void k_aux(float* __restrict__ out, int out_size) {
    __shared__ float part[256];
    __shared__ float colsum[NE];
    int tid = threadIdx.x;
    int e = tid & 31, p = tid >> 5;  // 8 partials per expert
    float s = 0.f;
    for (int t = p * (NT / 8); t < (p + 1) * (NT / 8); t++)
        s += d_probs[t * NE + e];
    part[tid] = s;
    __syncthreads();
    if (tid < NE) {
        float cs = 0.f;
        #pragma unroll
        for (int q = 0; q < 8; q++) cs += part[q * 32 + tid];
        colsum[tid] = cs;
    }
    __syncthreads();
    if (tid == 0) {
        float aux = 0.f;
        for (int e2 = 0; e2 < NE; e2++)
            aux += (colsum[e2] / (float)NT) * ((float)d_cnt[e2] / (float)NT);
        if (out_size > NT * TD) out[NT * TD] = aux;
    }
}

// ======================================================================
extern "C" void kernel_launch(void* const* d_in, const int* in_sizes, int n_in,
                              void* d_out, int out_size) {
    const float* x     = (const float*)d_in[0];
    const float* Wgate = (const float*)d_in[1];
    const float* Wg    = (const float*)d_in[2];
    const float* Wu    = (const float*)d_in[3];
    const float* Wd    = (const float*)d_in[4];
    float* out = (float*)d_out;

    k_init<<<1, 64>>>();
    k_router<<<NT / 8, 256>>>(x, Wgate);
    k_scan<<<1, 32>>>();
    k_build<<<NP / 256, 256>>>();

    dim3 gA(TI / BN, NT / BM, NE);   // 16 x 128 x 32 (most m-tiles early-exit)
    k_gateup<<<gA, NTHREADS>>>(x, Wg, Wu);

    dim3 gB(TD / BN, NT / BM, NE);   // 32 x 128 x 32
    k_down<<<gB, NTHREADS>>>(Wd);

    k_combine<<<NT, 256>>>(out);
    k_aux<<<1, 256>>>(out, out_size);
}

// round 4
// speedup vs baseline: 1.1041x; 1.1041x over previous
#include <cuda_runtime.h>
#include <math.h>
#include <stdint.h>

// ---- problem dims ----
#define TD 2048      // hidden
#define TI 1024      // intermediate
#define NE 32        // experts
#define KE 8         // top-k
#define NT 8192      // tokens (4*2048)
#define NP (NT*KE)   // 65536 token-expert pairs

// ---- GEMM tiles (128x128 block, 256 threads, 8 warps of 64x32) ----
#define BM 128
#define BN 128
#define BK 16
#define NTHREADS 256
#define APAD 20      // smem row stride for A tiles (conflict-free frag loads)
#define BPAD 136     // smem row stride for B tiles (conflict-free: tg*8+g)

#define SMEM_A_WORDS   (2 * BM * APAD)      // 5120
#define SMEM_B_WORDS   (2 * BK * BPAD)      // 4352
#define SMEM_GATEUP_B  ((SMEM_A_WORDS + 2 * SMEM_B_WORDS) * 4)   // 55296 bytes

// ---- scratch (no allocations allowed -> __device__ globals) ----
__device__ int   d_cnt[NE];
__device__ int   d_off[NE+1];
__device__ int   d_cursor[NE];
__device__ int   d_topi[NT*KE];
__device__ float d_topw[NT*KE];
__device__ float d_probs[NT*NE];
__device__ int   d_ltok[NP];
__device__ float d_lw[NP];
__device__ int   d_ppos[NT*KE];
__device__ float d_h[(size_t)NP*TI];   // 256 MiB
__device__ float d_y[(size_t)NP*TD];   // 512 MiB

// ======================================================================
// helpers
// ======================================================================
__device__ __forceinline__ uint32_t f2tf32(float x) {
    uint32_t r;
    asm("cvt.rna.tf32.f32 %0, %1;" : "=r"(r) : "f"(x));
    return r;
}

__device__ __forceinline__ void mma_tf32(float c[4], const uint32_t a[4], const uint32_t b[2]) {
    asm volatile(
        "mma.sync.aligned.m16n8k8.row.col.f32.tf32.tf32.f32 "
        "{%0,%1,%2,%3}, {%4,%5,%6,%7}, {%8,%9}, {%0,%1,%2,%3};\n"
        : "+f"(c[0]), "+f"(c[1]), "+f"(c[2]), "+f"(c[3])
        : "r"(a[0]), "r"(a[1]), "r"(a[2]), "r"(a[3]), "r"(b[0]), "r"(b[1]));
}

// ======================================================================
// 0) init scratch counters
// ======================================================================
__global__ void k_init() {
    int i = threadIdx.x;
    if (i < NE) { d_cnt[i] = 0; d_cursor[i] = 0; }
}

// ======================================================================
// 1) router: logits, top-8 (lower-index tie-break), softmax(top-k),
//    full softmax probs (for aux), per-expert counts
// ======================================================================
__global__ void k_router(const float* __restrict__ X, const float* __restrict__ Wgate) {
    int warp = threadIdx.x >> 5, lane = threadIdx.x & 31;
    int t = blockIdx.x * 8 + warp;
    __shared__ int scnt[NE];
    if (threadIdx.x < NE) scnt[threadIdx.x] = 0;
    __syncthreads();

    const float4* x4 = (const float4*)(X + (size_t)t * TD);
    float acc = 0.f;
    #pragma unroll 4
    for (int d4 = 0; d4 < TD / 4; d4++) {
        float4 xv = __ldg(&x4[d4]);
        int d = d4 * 4;
        acc += xv.x * __ldg(&Wgate[(d + 0) * NE + lane]);
        acc += xv.y * __ldg(&Wgate[(d + 1) * NE + lane]);
        acc += xv.z * __ldg(&Wgate[(d + 2) * NE + lane]);
        acc += xv.w * __ldg(&Wgate[(d + 3) * NE + lane]);
    }
    float vo = acc;     // original logit for expert==lane
    float v  = acc;     // working copy for top-k

    float topv[KE]; int topidx[KE];
    #pragma unroll
    for (int k = 0; k < KE; k++) {
        float mv = v; int mi = lane;
        #pragma unroll
        for (int off = 16; off > 0; off >>= 1) {
            float ov = __shfl_xor_sync(0xffffffffu, mv, off);
            int   oi = __shfl_xor_sync(0xffffffffu, mi, off);
            if (ov > mv || (ov == mv && oi < mi)) { mv = ov; mi = oi; }
        }
        topv[k] = mv; topidx[k] = mi;
        if (lane == mi) v = -INFINITY;
    }

    // softmax over the selected 8
    float m = topv[0];
    float s = 0.f;
    #pragma unroll
    for (int k = 0; k < KE; k++) s += expf(topv[k] - m);
    #pragma unroll
    for (int k = 0; k < KE; k++) {
        if (lane == k) {
            d_topi[t * KE + k] = topidx[k];
            d_topw[t * KE + k] = expf(topv[k] - m) / s;
        }
        if (lane == 0) atomicAdd(&scnt[topidx[k]], 1);
    }

    // full-softmax probs for aux loss
    float pe = expf(vo - m);
    float ps = pe;
    #pragma unroll
    for (int off = 16; off > 0; off >>= 1) ps += __shfl_xor_sync(0xffffffffu, ps, off);
    d_probs[t * NE + lane] = pe / ps;

    __syncthreads();
    if (threadIdx.x < NE) atomicAdd(&d_cnt[threadIdx.x], scnt[threadIdx.x]);
}

// ======================================================================
// 2) exclusive scan of counts (tiny)
// ======================================================================
__global__ void k_scan() {
    if (threadIdx.x == 0) {
        int s = 0;
        for (int e = 0; e < NE; e++) { d_off[e] = s; s += d_cnt[e]; }
        d_off[NE] = s;
    }
}

// ======================================================================
// 3) build per-expert token lists + pair-position index (gather combine)
// ======================================================================
__global__ void k_build() {
    int i = blockIdx.x * blockDim.x + threadIdx.x;
    if (i >= NP) return;
    int e   = d_topi[i];
    int pos = atomicAdd(&d_cursor[e], 1);
    int idx = d_off[e] + pos;
    d_ltok[idx] = i >> 3;     // token id
    d_lw[idx]   = d_topw[i];
    d_ppos[i]   = idx;
}

// ======================================================================
// 4) pass A: h = silu(X_e @ Wg_e) * (X_e @ Wu_e), gathered rows, tf32 mma
//    grid: (TI/BN, NT/BM, NE)   block 128x128, warp tile 64x32
// ======================================================================
__global__ __launch_bounds__(NTHREADS, 1) void k_gateup(const float* __restrict__ X,
                                                        const float* __restrict__ Wg,
                                                        const float* __restrict__ Wu) {
    int e  = blockIdx.z;
    int Ce = d_cnt[e];
    int m0 = blockIdx.y * BM;
    if (m0 >= Ce) return;
    int n0   = blockIdx.x * BN;
    int gOff = d_off[e];
    const float* Bg = Wg + (size_t)e * TD * TI;
    const float* Bu = Wu + (size_t)e * TD * TI;

    extern __shared__ uint32_t smem[];
    uint32_t* sA  = smem;                               // [2][BM*APAD]
    uint32_t* sBg = smem + SMEM_A_WORDS;                // [2][BK*BPAD]
    uint32_t* sBu = sBg + SMEM_B_WORDS;                 // [2][BK*BPAD]

    int tid = threadIdx.x;
    int lane = tid & 31, warp = tid >> 5;
    int wm = warp & 1, wn = warp >> 1;          // 2 x 4 warp grid
    int g = lane >> 2, tg = lane & 3;

    // A loader: 128 rows x 4 float4 = 512 float4, 2 per thread
    int arow[2], acol[2];
    const float4* aptr[2];
    #pragma unroll
    for (int j = 0; j < 2; j++) {
        int lin = tid + j * 256;
        arow[j] = lin >> 2;
        acol[j] = (lin & 3) * 4;
        int r = m0 + arow[j]; if (r >= Ce) r = Ce - 1;
        int tok = d_ltok[gOff + r];
        aptr[j] = (const float4*)(X + (size_t)tok * TD + acol[j]);
    }
    // B loader: 16 rows x 32 float4 = 512 float4, 2 per thread (per matrix)
    int brow[2], bcol[2];
    #pragma unroll
    for (int j = 0; j < 2; j++) {
        int lin = tid + j * 256;
        brow[j] = lin >> 5;
        bcol[j] = (lin & 31) * 4;
    }

    float cg[4][4][4], cu[4][4][4];
    #pragma unroll
    for (int a = 0; a < 4; a++)
        #pragma unroll
        for (int b = 0; b < 4; b++)
            #pragma unroll
            for (int c = 0; c < 4; c++) { cg[a][b][c] = 0.f; cu[a][b][c] = 0.f; }

    const int KT = TD / BK;  // 128
    float4 ra[2], rg[2], ru[2];

    // prologue: load tile 0
    #pragma unroll
    for (int j = 0; j < 2; j++) {
        ra[j] = __ldg(aptr[j]);
        rg[j] = __ldg((const float4*)(Bg + (size_t)brow[j] * TI + n0 + bcol[j]));
        ru[j] = __ldg((const float4*)(Bu + (size_t)brow[j] * TI + n0 + bcol[j]));
    }
    #pragma unroll
    for (int j = 0; j < 2; j++) {
        uint32_t* pa = &sA[arow[j] * APAD + acol[j]];
        pa[0] = f2tf32(ra[j].x); pa[1] = f2tf32(ra[j].y); pa[2] = f2tf32(ra[j].z); pa[3] = f2tf32(ra[j].w);
        uint32_t* pg = &sBg[brow[j] * BPAD + bcol[j]];
        pg[0] = f2tf32(rg[j].x); pg[1] = f2tf32(rg[j].y); pg[2] = f2tf32(rg[j].z); pg[3] = f2tf32(rg[j].w);
        uint32_t* pu = &sBu[brow[j] * BPAD + bcol[j]];
        pu[0] = f2tf32(ru[j].x); pu[1] = f2tf32(ru[j].y); pu[2] = f2tf32(ru[j].z); pu[3] = f2tf32(ru[j].w);
    }
    __syncthreads();

    for (int kt = 0; kt < KT; kt++) {
        int buf = kt & 1;
        int aoff = buf * (BM * APAD);
        int boff = buf * (BK * BPAD);
        if (kt + 1 < KT) {
            int k0 = (kt + 1) * BK;
            #pragma unroll
            for (int j = 0; j < 2; j++) {
                ra[j] = __ldg(aptr[j] + (k0 >> 2));
                rg[j] = __ldg((const float4*)(Bg + (size_t)(k0 + brow[j]) * TI + n0 + bcol[j]));
                ru[j] = __ldg((const float4*)(Bu + (size_t)(k0 + brow[j]) * TI + n0 + bcol[j]));
            }
        }
        // compute on buf
        #pragma unroll
        for (int ks = 0; ks < 2; ks++) {
            int kk = ks * 8;
            uint32_t afr[4][4];
            #pragma unroll
            for (int mf = 0; mf < 4; mf++) {
                int r = wm * 64 + mf * 16;
                afr[mf][0] = sA[aoff + (r + g)     * APAD + kk + tg];
                afr[mf][1] = sA[aoff + (r + g + 8) * APAD + kk + tg];
                afr[mf][2] = sA[aoff + (r + g)     * APAD + kk + tg + 4];
                afr[mf][3] = sA[aoff + (r + g + 8) * APAD + kk + tg + 4];
            }
            uint32_t bfg[4][2], bfu[4][2];
            #pragma unroll
            for (int nf = 0; nf < 4; nf++) {
                int c = wn * 32 + nf * 8 + g;
                bfg[nf][0] = sBg[boff + (kk + tg)     * BPAD + c];
                bfg[nf][1] = sBg[boff + (kk + tg + 4) * BPAD + c];
                bfu[nf][0] = sBu[boff + (kk + tg)     * BPAD + c];
                bfu[nf][1] = sBu[boff + (kk + tg + 4) * BPAD + c];
            }
            #pragma unroll
            for (int mf = 0; mf < 4; mf++)
                #pragma unroll
                for (int nf = 0; nf < 4; nf++) {
                    mma_tf32(cg[mf][nf], afr[mf], bfg[nf]);
                    mma_tf32(cu[mf][nf], afr[mf], bfu[nf]);
                }
        }
        if (kt + 1 < KT) {
            int nb = (buf ^ 1);
            int naoff = nb * (BM * APAD);
            int nboff = nb * (BK * BPAD);
            #pragma unroll
            for (int j = 0; j < 2; j++) {
                uint32_t* pa = &sA[naoff + arow[j] * APAD + acol[j]];
                pa[0] = f2tf32(ra[j].x); pa[1] = f2tf32(ra[j].y); pa[2] = f2tf32(ra[j].z); pa[3] = f2tf32(ra[j].w);
                uint32_t* pg = &sBg[nboff + brow[j] * BPAD + bcol[j]];
                pg[0] = f2tf32(rg[j].x); pg[1] = f2tf32(rg[j].y); pg[2] = f2tf32(rg[j].z); pg[3] = f2tf32(rg[j].w);
                uint32_t* pu = &sBu[nboff + brow[j] * BPAD + bcol[j]];
                pu[0] = f2tf32(ru[j].x); pu[1] = f2tf32(ru[j].y); pu[2] = f2tf32(ru[j].z); pu[3] = f2tf32(ru[j].w);
            }
        }
        __syncthreads();
    }

    // epilogue: fused SiLU * up -> h
    #pragma unroll
    for (int mf = 0; mf < 4; mf++) {
        #pragma unroll
        for (int nf = 0; nf < 4; nf++) {
            int r0 = wm * 64 + mf * 16 + g;
            int c  = n0 + wn * 32 + nf * 8 + tg * 2;
            #pragma unroll
            for (int hh = 0; hh < 2; hh++) {
                int grow = m0 + r0 + hh * 8;
                if (grow < Ce) {
                    float g0 = cg[mf][nf][hh * 2 + 0], g1 = cg[mf][nf][hh * 2 + 1];
                    float u0 = cu[mf][nf][hh * 2 + 0], u1 = cu[mf][nf][hh * 2 + 1];
                    float s0 = g0 / (1.f + __expf(-g0)) * u0;
                    float s1 = g1 / (1.f + __expf(-g1)) * u1;
                    *(float2*)&d_h[(size_t)(gOff + grow) * TI + c] = make_float2(s0, s1);
                }
            }
        }
    }
}

// ======================================================================
// 5) pass B: y = (w * h) @ Wd_e     grid: (TD/BN, NT/BM, NE)
//    block 128x128, warp tile 64x32
// ======================================================================
__global__ __launch_bounds__(NTHREADS, 1) void k_down(const float* __restrict__ Wd) {
    int e  = blockIdx.z;
    int Ce = d_cnt[e];
    int m0 = blockIdx.y * BM;
    if (m0 >= Ce) return;
    int n0   = blockIdx.x * BN;
    int gOff = d_off[e];
    const float* Bw = Wd + (size_t)e * TI * TD;

    __shared__ uint32_t sA[2 * BM * APAD];
    __shared__ uint32_t sB[2 * BK * BPAD];

    int tid = threadIdx.x;
    int lane = tid & 31, warp = tid >> 5;
    int wm = warp & 1, wn = warp >> 1;
    int g = lane >> 2, tg = lane & 3;

    int arow[2], acol[2];
    const float4* aptr[2];
    #pragma unroll
    for (int j = 0; j < 2; j++) {
        int lin = tid + j * 256;
        arow[j] = lin >> 2;
        acol[j] = (lin & 3) * 4;
        int r = m0 + arow[j]; if (r >= Ce) r = Ce - 1;
        aptr[j] = (const float4*)(d_h + (size_t)(gOff + r) * TI + acol[j]);
    }
    int brow[2], bcol[2];
    #pragma unroll
    for (int j = 0; j < 2; j++) {
        int lin = tid + j * 256;
        brow[j] = lin >> 5;
        bcol[j] = (lin & 31) * 4;
    }

    float cc[4][4][4];
    #pragma unroll
    for (int a = 0; a < 4; a++)
        #pragma unroll
        for (int b = 0; b < 4; b++)
            #pragma unroll
            for (int c = 0; c < 4; c++) cc[a][b][c] = 0.f;

    const int KT = TI / BK;  // 64
    float4 ra[2], rb[2];

    #pragma unroll
    for (int j = 0; j < 2; j++) {
        ra[j] = __ldg(aptr[j]);
        rb[j] = __ldg((const float4*)(Bw + (size_t)brow[j] * TD + n0 + bcol[j]));
    }
    #pragma unroll
    for (int j = 0; j < 2; j++) {
        uint32_t* pa = &sA[arow[j] * APAD + acol[j]];
        pa[0] = f2tf32(ra[j].x); pa[1] = f2tf32(ra[j].y); pa[2] = f2tf32(ra[j].z); pa[3] = f2tf32(ra[j].w);
        uint32_t* pb = &sB[brow[j] * BPAD + bcol[j]];
        pb[0] = f2tf32(rb[j].x); pb[1] = f2tf32(rb[j].y); pb[2] = f2tf32(rb[j].z); pb[3] = f2tf32(rb[j].w);
    }
    __syncthreads();

    for (int kt = 0; kt < KT; kt++) {
        int buf = kt & 1;
        int aoff = buf * (BM * APAD);
        int boff = buf * (BK * BPAD);
        if (kt + 1 < KT) {
            int k0 = (kt + 1) * BK;
            #pragma unroll
            for (int j = 0; j < 2; j++) {
                ra[j] = __ldg(aptr[j] + (k0 >> 2));
                rb[j] = __ldg((const float4*)(Bw + (size_t)(k0 + brow[j]) * TD + n0 + bcol[j]));
            }
        }
        #pragma unroll
        for (int ks = 0; ks < 2; ks++) {
            int kk = ks * 8;
            uint32_t afr[4][4];
            #pragma unroll
            for (int mf = 0; mf < 4; mf++) {
                int r = wm * 64 + mf * 16;
                afr[mf][0] = sA[aoff + (r + g)     * APAD + kk + tg];
                afr[mf][1] = sA[aoff + (r + g + 8) * APAD + kk + tg];
                afr[mf][2] = sA[aoff + (r + g)     * APAD + kk + tg + 4];
                afr[mf][3] = sA[aoff + (r + g + 8) * APAD + kk + tg + 4];
            }
            uint32_t bfr[4][2];
            #pragma unroll
            for (int nf = 0; nf < 4; nf++) {
                int c = wn * 32 + nf * 8 + g;
                bfr[nf][0] = sB[boff + (kk + tg)     * BPAD + c];
                bfr[nf][1] = sB[boff + (kk + tg + 4) * BPAD + c];
            }
            #pragma unroll
            for (int mf = 0; mf < 4; mf++)
                #pragma unroll
                for (int nf = 0; nf < 4; nf++)
                    mma_tf32(cc[mf][nf], afr[mf], bfr[nf]);
        }
        if (kt + 1 < KT) {
            int nb = (buf ^ 1);
            int naoff = nb * (BM * APAD);
            int nboff = nb * (BK * BPAD);
            #pragma unroll
            for (int j = 0; j < 2; j++) {
                uint32_t* pa = &sA[naoff + arow[j] * APAD + acol[j]];
                pa[0] = f2tf32(ra[j].x); pa[1] = f2tf32(ra[j].y); pa[2] = f2tf32(ra[j].z); pa[3] = f2tf32(ra[j].w);
                uint32_t* pb = &sB[nboff + brow[j] * BPAD + bcol[j]];
                pb[0] = f2tf32(rb[j].x); pb[1] = f2tf32(rb[j].y); pb[2] = f2tf32(rb[j].z); pb[3] = f2tf32(rb[j].w);
            }
        }
        __syncthreads();
    }

    // epilogue: scale by router weight, store y
    #pragma unroll
    for (int mf = 0; mf < 4; mf++) {
        #pragma unroll
        for (int nf = 0; nf < 4; nf++) {
            int r0 = wm * 64 + mf * 16 + g;
            int c  = n0 + wn * 32 + nf * 8 + tg * 2;
            #pragma unroll
            for (int hh = 0; hh < 2; hh++) {
                int grow = m0 + r0 + hh * 8;
                if (grow < Ce) {
                    float w = d_lw[gOff + grow];
                    float v0 = w * cc[mf][nf][hh * 2 + 0];
                    float v1 = w * cc[mf][nf][hh * 2 + 1];
                    *(float2*)&d_y[(size_t)(gOff + grow) * TD + c] = make_float2(v0, v1);
                }
            }
        }
    }
}

// ======================================================================
// 6) combine: out[t] = sum_k y[pairpos(t,k)]   (gather, deterministic)
// ======================================================================
__global__ void k_combine(float* __restrict__ out) {
    int t = blockIdx.x;
    __shared__ int pp[KE];
    if (threadIdx.x < KE) pp[threadIdx.x] = d_ppos[t * KE + threadIdx.x];
    __syncthreads();
    int tid = threadIdx.x;  // 256 threads
    #pragma unroll
    for (int part = 0; part < 2; part++) {
        int c4 = tid + part * 256;  // float4 index within row (512 total)
        float4 acc = make_float4(0.f, 0.f, 0.f, 0.f);
        #pragma unroll
        for (int k = 0; k < KE; k++) {
            float4 v = __ldg((const float4*)&d_y[(size_t)pp[k] * TD] + c4);
            acc.x += v.x; acc.y += v.y; acc.z += v.z; acc.w += v.w;
        }
        ((float4*)(out + (size_t)t * TD))[c4] = acc;
    }
}

// ======================================================================
// 7) aux loss = sum_e mean_t(probs[t,e]) * cnt_e / T   (deterministic)
// ======================================================================
__global__ void k_aux(float* __restrict__ out, int out_size) {
    __shared__ float part[256];
    __shared__ float colsum[NE];
    int tid = threadIdx.x;
    int e = tid & 31, p = tid >> 5;  // 8 partials per expert
    float s = 0.f;
    for (int t = p * (NT / 8); t < (p + 1) * (NT / 8); t++)
        s += d_probs[t * NE + e];
    part[tid] = s;
    __syncthreads();
    if (tid < NE) {
        float cs = 0.f;
        #pragma unroll
        for (int q = 0; q < 8; q++) cs += part[q * 32 + tid];
        colsum[tid] = cs;
    }
    __syncthreads();
    if (tid == 0) {
        float aux = 0.f;
        for (int e2 = 0; e2 < NE; e2++)
            aux += (colsum[e2] / (float)NT) * ((float)d_cnt[e2] / (float)NT);
        if (out_size > NT * TD) out[NT * TD] = aux;
    }
}

// ======================================================================
extern "C" void kernel_launch(void* const* d_in, const int* in_sizes, int n_in,
                              void* d_out, int out_size) {
    const float* x     = (const float*)d_in[0];
    const float* Wgate = (const float*)d_in[1];
    const float* Wg    = (const float*)d_in[2];
    const float* Wu    = (const float*)d_in[3];
    const float* Wd    = (const float*)d_in[4];
    float* out = (float*)d_out;

    // gateup needs >48KB smem -> opt-in (idempotent, capture-safe: not a stream op)
    cudaFuncSetAttribute(k_gateup, cudaFuncAttributeMaxDynamicSharedMemorySize, SMEM_GATEUP_B);

    k_init<<<1, 64>>>();
    k_router<<<NT / 8, 256>>>(x, Wgate);
    k_scan<<<1, 32>>>();
    k_build<<<NP / 256, 256>>>();

    dim3 gA(TI / BN, NT / BM, NE);   // 8 x 64 x 32 (most m-tiles early-exit)
    k_gateup<<<gA, NTHREADS, SMEM_GATEUP_B>>>(x, Wg, Wu);

    dim3 gB(TD / BN, NT / BM, NE);   // 16 x 64 x 32
    k_down<<<gB, NTHREADS>>>(Wd);

    k_combine<<<NT, 256>>>(out);
    k_aux<<<1, 256>>>(out, out_size);
}